// round 15
// baseline (speedup 1.0000x reference)
#include <cuda_runtime.h>
#include <math.h>
#include <math_constants.h>

#define FULL 0xffffffffu

__device__ __forceinline__ float warp_sum(float v) {
#pragma unroll
    for (int o = 16; o > 0; o >>= 1) v += __shfl_xor_sync(FULL, v, o);
    return v;
}
__device__ __forceinline__ float warp_max(float v) {
#pragma unroll
    for (int o = 16; o > 0; o >>= 1) v = fmaxf(v, __shfl_xor_sync(FULL, v, o));
    return v;
}

// ---- scratch (allocation-free: __device__ globals) ----
__device__ float g_kv[32 * 129 * 64];   // row 0: target emb, rows 1..128: map emb (only first 32 floats used)
__device__ float g_Af[32 * 32];         // A folded over both dims
__device__ float g_wf2[32];             // folded score-bias vector
__device__ float g_M0f[32 * 64];        // M0 rows folded
__device__ float g_c0[64];
__device__ float g_M1[64 * 64], g_c1[64];
__device__ float g_M2[64 * 64], g_c2[64];
__device__ float g_ta[32 * 64];
__device__ float g_u[32 * 64];
__device__ float g_csc[32];
__device__ int   g_cnt[32];

// in-thread LayerNorm + affine + relu over 32 register channels (ILP'd sums)
__device__ __forceinline__ void ln_relu32(float* h, const float* g, const float* be) {
    float p0 = 0.f, p1 = 0.f, p2 = 0.f, p3 = 0.f;
#pragma unroll
    for (int c = 0; c < 32; c += 4) { p0 += h[c]; p1 += h[c+1]; p2 += h[c+2]; p3 += h[c+3]; }
    float mu = (p0 + p1 + p2 + p3) * 0.03125f;
    float v0 = 0.f, v1 = 0.f, v2 = 0.f, v3 = 0.f;
#pragma unroll
    for (int c = 0; c < 32; c += 4) {
        float d0 = h[c] - mu, d1 = h[c+1] - mu, d2 = h[c+2] - mu, d3 = h[c+3] - mu;
        v0 = fmaf(d0, d0, v0); v1 = fmaf(d1, d1, v1);
        v2 = fmaf(d2, d2, v2); v3 = fmaf(d3, d3, v3);
    }
    float rs = rsqrtf((v0 + v1 + v2 + v3) * 0.03125f + 1e-5f);
#pragma unroll
    for (int c = 0; c < 32; c++)
        h[c] = fmaxf(fmaf((h[c] - mu) * rs, g[c], be[c]), 0.f);
}

// ============================================================
// Kernel 1: local graphs (thread-per-row) + all weight folds.
// ============================================================
constexpr int GRAPH_SMEM_FLOATS = 1792 + 320 * 36;
constexpr int GRAPH_SMEM_BYTES  = GRAPH_SMEM_FLOATS * 4;

__global__ __launch_bounds__(320) void k_graph(
    const float* __restrict__ mxs,
    const float* __restrict__ mW1, const float* __restrict__ mb1,
    const float* __restrict__ mg1, const float* __restrict__ mbe1,
    const float* __restrict__ mW2, const float* __restrict__ mb2,
    const float* __restrict__ mg2, const float* __restrict__ mbe2,
    const float* __restrict__ axs,
    const float* __restrict__ aW1, const float* __restrict__ ab1,
    const float* __restrict__ ag1, const float* __restrict__ abe1,
    const float* __restrict__ aW2, const float* __restrict__ ab2,
    const float* __restrict__ ag2, const float* __restrict__ abe2,
    const float* __restrict__ att_Wv, const float* __restrict__ att_bv,
    const float* __restrict__ att_Wo, const float* __restrict__ att_bo,
    const float* __restrict__ att_Wq, const float* __restrict__ att_bq,
    const float* __restrict__ att_Wk)
{
    extern __shared__ float sm[];
    int tid = threadIdx.x;
    int bb = blockIdx.x;

    if (bb < 256) {
        // ---------------- map path: thread = one (b,m,p) row ----------------
        float* sW1 = sm;            // 16*32
        float* sW2 = sm + 512;      // 32*32
        float* sb1 = sm + 1536; float* sg1 = sm + 1568; float* sbe1 = sm + 1600;
        float* sb2 = sm + 1632; float* sg2 = sm + 1664; float* sbe2 = sm + 1696;
        float* se  = sm + 1792;     // 320*36

        if (tid < 128) ((float4*)sW1)[tid] = ((const float4*)mW1)[tid];
        for (int t = tid; t < 256; t += 320)
            ((float4*)sW2)[t] = ((const float4*)mW2)[t];
        if (tid >= 128 && tid < 160) {
            int c = tid - 128;
            sb1[c] = mb1[c]; sg1[c] = mg1[c]; sbe1[c] = mbe1[c];
            sb2[c] = mb2[c]; sg2[c] = mg2[c]; sbe2[c] = mbe2[c];
        }
        __syncthreads();

        size_t row = (size_t)bb * 320 + tid;
        float x[16];
        {
            const float4* xg = (const float4*)(mxs + row * 16);
            float4 a = xg[0], b_ = xg[1], c = xg[2], d = xg[3];
            x[0]=a.x; x[1]=a.y; x[2]=a.z; x[3]=a.w;
            x[4]=b_.x; x[5]=b_.y; x[6]=b_.z; x[7]=b_.w;
            x[8]=c.x; x[9]=c.y; x[10]=c.z; x[11]=c.w;
            x[12]=d.x; x[13]=d.y; x[14]=d.z; x[15]=d.w;
        }

        float h[32];
#pragma unroll
        for (int c4 = 0; c4 < 8; c4++) {
            float4 b4 = ((const float4*)sb1)[c4];
            h[c4*4+0]=b4.x; h[c4*4+1]=b4.y; h[c4*4+2]=b4.z; h[c4*4+3]=b4.w;
        }
#pragma unroll
        for (int k = 0; k < 16; k++) {
            float xv = x[k];
#pragma unroll
            for (int c4 = 0; c4 < 8; c4++) {
                float4 w = ((const float4*)sW1)[k * 8 + c4];
                h[c4*4+0] = fmaf(xv, w.x, h[c4*4+0]);
                h[c4*4+1] = fmaf(xv, w.y, h[c4*4+1]);
                h[c4*4+2] = fmaf(xv, w.z, h[c4*4+2]);
                h[c4*4+3] = fmaf(xv, w.w, h[c4*4+3]);
            }
        }
        ln_relu32(h, sg1, sbe1);

        float a2[32];
#pragma unroll
        for (int c4 = 0; c4 < 8; c4++) {
            float4 b4 = ((const float4*)sb2)[c4];
            a2[c4*4+0]=b4.x; a2[c4*4+1]=b4.y; a2[c4*4+2]=b4.z; a2[c4*4+3]=b4.w;
        }
#pragma unroll
        for (int k = 0; k < 32; k++) {
            float hv = h[k];
#pragma unroll
            for (int c4 = 0; c4 < 8; c4++) {
                float4 w = ((const float4*)sW2)[k * 8 + c4];
                a2[c4*4+0] = fmaf(hv, w.x, a2[c4*4+0]);
                a2[c4*4+1] = fmaf(hv, w.y, a2[c4*4+1]);
                a2[c4*4+2] = fmaf(hv, w.z, a2[c4*4+2]);
                a2[c4*4+3] = fmaf(hv, w.w, a2[c4*4+3]);
            }
        }
        ln_relu32(a2, sg2, sbe2);

#pragma unroll
        for (int c4 = 0; c4 < 8; c4++)
            ((float4*)(se + tid * 36))[c4] =
                make_float4(a2[c4*4+0], a2[c4*4+1], a2[c4*4+2], a2[c4*4+3]);
        __syncthreads();

        int w = tid >> 5, lane = tid & 31;
        for (int g = w; g < 16; g += 10) {
            const float* base = se + (g * 20) * 36 + lane;
            float mx = base[0];
#pragma unroll
            for (int j = 1; j < 20; j++) mx = fmaxf(mx, base[j * 36]);
            int bm = bb * 16 + g;
            int b = bm >> 7, m = bm & 127;
            g_kv[((size_t)b * 129 + 1 + m) * 64 + lane] = mx;   // upper half dead
        }
    } else if (bb < 260) {
        // ---------------- agent path (agent 0) ----------------
        float* aW1s = sm;           // 4*32
        float* aW2s = sm + 512;     // 32*32
        float* ab1s = sm + 1536; float* ag1s = sm + 1568; float* abe1s = sm + 1600;
        float* ab2s = sm + 1632; float* ag2s = sm + 1664; float* abe2s = sm + 1696;
        float* se   = sm + 1792;    // 256*36

        if (tid < 32) ((float4*)aW1s)[tid] = ((const float4*)aW1)[tid];
        else if (tid < 288) ((float4*)aW2s)[tid - 32] = ((const float4*)aW2)[tid - 32];
        if (tid >= 288) {
            int t = tid - 288;
            ab1s[t] = ab1[t]; ag1s[t] = ag1[t]; abe1s[t] = abe1[t];
            ab2s[t] = ab2[t]; ag2s[t] = ag2[t]; abe2s[t] = abe2[t];
        }
        __syncthreads();

        if (tid < 256) {
            int b0 = (bb - 256) * 8;
            int lb = tid >> 5, row = tid & 31;
            int b = b0 + lb;
            float4 xv4 = ((const float4*)(axs + (size_t)b * 4096 + row * 4))[0];

            float h[32];
#pragma unroll
            for (int c4 = 0; c4 < 8; c4++) {
                float4 b4 = ((const float4*)ab1s)[c4];
                h[c4*4+0]=b4.x; h[c4*4+1]=b4.y; h[c4*4+2]=b4.z; h[c4*4+3]=b4.w;
            }
            float xk[4] = {xv4.x, xv4.y, xv4.z, xv4.w};
#pragma unroll
            for (int k = 0; k < 4; k++) {
                float xv = xk[k];
#pragma unroll
                for (int c4 = 0; c4 < 8; c4++) {
                    float4 w = ((const float4*)aW1s)[k * 8 + c4];
                    h[c4*4+0] = fmaf(xv, w.x, h[c4*4+0]);
                    h[c4*4+1] = fmaf(xv, w.y, h[c4*4+1]);
                    h[c4*4+2] = fmaf(xv, w.z, h[c4*4+2]);
                    h[c4*4+3] = fmaf(xv, w.w, h[c4*4+3]);
                }
            }
            ln_relu32(h, ag1s, abe1s);

            float a2[32];
#pragma unroll
            for (int c4 = 0; c4 < 8; c4++) {
                float4 b4 = ((const float4*)ab2s)[c4];
                a2[c4*4+0]=b4.x; a2[c4*4+1]=b4.y; a2[c4*4+2]=b4.z; a2[c4*4+3]=b4.w;
            }
#pragma unroll
            for (int k = 0; k < 32; k++) {
                float hv = h[k];
#pragma unroll
                for (int c4 = 0; c4 < 8; c4++) {
                    float4 w = ((const float4*)aW2s)[k * 8 + c4];
                    a2[c4*4+0] = fmaf(hv, w.x, a2[c4*4+0]);
                    a2[c4*4+1] = fmaf(hv, w.y, a2[c4*4+1]);
                    a2[c4*4+2] = fmaf(hv, w.z, a2[c4*4+2]);
                    a2[c4*4+3] = fmaf(hv, w.w, a2[c4*4+3]);
                }
            }
            ln_relu32(a2, ag2s, abe2s);

#pragma unroll
            for (int c4 = 0; c4 < 8; c4++)
                ((float4*)(se + tid * 36))[c4] =
                    make_float4(a2[c4*4+0], a2[c4*4+1], a2[c4*4+2], a2[c4*4+3]);
        }
        __syncthreads();

        int w = tid >> 5, lane = tid & 31;
        if (w < 8) {
            const float* base = se + (w * 32) * 36 + lane;
            float mx = base[0];
#pragma unroll
            for (int j = 1; j < 32; j++) mx = fmaxf(mx, base[j * 36]);
            int b = (bb - 256) * 8 + w;
            g_kv[(size_t)b * 129 * 64 + lane] = mx;   // upper half dead
        }
    } else if (bb < 284) {
        // ---------------- M folds ----------------
        float* sWo = sm;            // 4096
        float* sWv = sm + 4096;     // up to 512

        int which = bb - 260;
        int head  = which >> 3, sub = which & 7;
        const float* Wv = att_Wv + head * 4096;
        const float* Wo = att_Wo + head * 4096;
        const float* bv = att_bv + head * 64;
        const float* bo = att_bo + head * 64;

        for (int t = tid; t < 1024; t += 320)
            ((float4*)sWo)[t] = ((const float4*)Wo)[t];

        if (head == 0) {
            int r0 = sub * 4;
            for (int t = tid; t < 256; t += 320) {
                int r = t >> 6, d = t & 63;
                sWv[t] = Wv[(r0 + r) * 64 + d] + Wv[(r0 + r + 32) * 64 + d];
            }
            __syncthreads();
            for (int t = tid; t < 256; t += 320) {
                int r = t >> 6, d = t & 63;
                float acc = 0.f;
#pragma unroll 8
                for (int k = 0; k < 64; k++)
                    acc = fmaf(sWv[r * 64 + k], sWo[k * 64 + d], acc);
                g_M0f[(r0 + r) * 64 + d] = acc;
            }
            if (sub == 0 && tid >= 256) {
                int d = tid - 256;
                if (d < 64) {
                    float acc = bo[d];
#pragma unroll 8
                    for (int k = 0; k < 64; k++)
                        acc = fmaf(bv[k], sWo[k * 64 + d], acc);
                    g_c0[d] = acc;
                }
            }
        } else {
            int r0 = sub * 8;
            float* M    = (head == 1) ? g_M1 : g_M2;
            float* cvec = (head == 1) ? g_c1 : g_c2;
            if (tid < 128)
                ((float4*)sWv)[tid] = ((const float4*)(Wv + r0 * 64))[tid];
            __syncthreads();
            for (int t = tid; t < 512; t += 320) {
                int r = t >> 6, d = t & 63;
                float acc = 0.f;
#pragma unroll 8
                for (int k = 0; k < 64; k++)
                    acc = fmaf(sWv[r * 64 + k], sWo[k * 64 + d], acc);
                M[(r0 + r) * 64 + d] = acc;
            }
            if (sub == 0 && tid < 64) {
                int d = tid;
                float acc = bo[d];
#pragma unroll 8
                for (int k = 0; k < 64; k++)
                    acc = fmaf(bv[k], sWo[k * 64 + d], acc);
                cvec[d] = acc;
            }
        }
    } else {
        // ---------------- Af fold ----------------
        float* sWkTf = sm;          // 64*36
        float* sWqf  = sm + 2304;   // 4*64

        int sub = bb - 284;
        int r0 = sub * 4;
        const float* Wq0 = att_Wq;
        const float* Wk0 = att_Wk;
        const float* bq0 = att_bq;

        for (int t = tid; t < 2048; t += 320) {
            int c = t >> 6, d = t & 63;
            sWkTf[d * 36 + c] = Wk0[c * 64 + d] + Wk0[(c + 32) * 64 + d];
        }
        for (int t = tid; t < 256; t += 320) {
            int r = t >> 6, d = t & 63;
            sWqf[t] = Wq0[(r0 + r) * 64 + d] + Wq0[(r0 + r + 32) * 64 + d];
        }
        __syncthreads();

        if (tid < 128) {
            int r = tid >> 5, c = tid & 31;
            float acc = 0.f;
#pragma unroll 8
            for (int d = 0; d < 64; d++)
                acc = fmaf(sWqf[r * 64 + d], sWkTf[d * 36 + c], acc);
            g_Af[(r0 + r) * 32 + c] = acc;
        }
        if (sub == 0) {
            if (tid >= 128 && tid < 160) {
                int c = tid - 128;
                float acc = 0.f;
#pragma unroll 8
                for (int d = 0; d < 64; d++)
                    acc = fmaf(sWkTf[d * 36 + c], bq0[d], acc);
                g_wf2[c] = acc;
            } else if (tid >= 160 && tid < 192) {
                g_cnt[tid - 160] = 0;
            }
        }
    }
}

// ============================================================
// Kernel 2: attention (32-dim folded). 512 threads, 16 warps,
// ONE query per warp, 16 q/block, grid (8,32).  Warps/SM ~28.
// ============================================================
#define XS 36      // main X row stride
#define MEP 68     // tail me row stride
constexpr int ATTN_SMEM_FLOATS = 8960;
constexpr int ATTN_SMEM_BYTES = ATTN_SMEM_FLOATS * 4;

__global__ __launch_bounds__(512, 2)
void k_attn(
    const float* __restrict__ Wq2, const float* __restrict__ bq2,
    const float* __restrict__ Wk2, const float* __restrict__ bk2,
    float* __restrict__ out)
{
    extern __shared__ float smem[];
    // main-phase layout
    float* sX   = smem;             // 129*36 = 4644
    float* sS   = smem + 4644;      // 16*132 = 2112
    float* sY   = smem + 6756;      // 16*34  = 544
    float* sQt  = smem + 7300;      // 16*32  = 512
    float* sF   = smem + 7812;      // 132
    float* sWf2 = smem + 7944;      // 32
    float* sc0  = smem + 7976;      // 64
    __shared__ int sflag;
    __shared__ float sred[8];

    int b  = blockIdx.y;
    int q0 = blockIdx.x * 16;
    int tid = threadIdx.x;
    int w = tid >> 5, lane = tid & 31;
    int q = q0 + w;                 // this warp's query

    // ---- phase 1: stage 32-dim kv tile + wf2/c0 ----
    const float4* kv4 = (const float4*)(g_kv + (size_t)b * 129 * 64);
    for (int t = tid; t < 129 * 8; t += 512) {
        int r = t >> 3, d4 = t & 7;
        ((float4*)sX)[r * 9 + d4] = kv4[r * 16 + d4];
    }
    if (tid < 32) sWf2[tid] = g_wf2[tid];
    else if (tid < 96) sc0[tid - 32] = g_c0[tid - 32];
    __syncthreads();

    // ---- phase 2: Qt' = x32 @ Af (1 query/warp); f per key ----
    {
        const float* xq = sX + (1 + q) * XS;
        float p0 = 0.f, p1 = 0.f;
#pragma unroll 8
        for (int j = 0; j < 32; j += 2) {
            float a0 = __ldg(&g_Af[j * 32 + lane]);
            float a1 = __ldg(&g_Af[(j + 1) * 32 + lane]);
            p0 = fmaf(xq[j], a0, p0); p1 = fmaf(xq[j + 1], a1, p1);
        }
        sQt[w * 32 + lane] = p0 + p1;
    }
    if (tid < 129) {
        const float4* xk4 = (const float4*)(sX + tid * XS);
        const float4* wf4 = (const float4*)sWf2;
        float4 a = make_float4(0.f, 0.f, 0.f, 0.f);
#pragma unroll
        for (int j = 0; j < 8; j++) {
            float4 x = xk4[j], wv = wf4[j];
            a.x = fmaf(x.x, wv.x, a.x);
            a.y = fmaf(x.y, wv.y, a.y);
            a.z = fmaf(x.z, wv.z, a.z);
            a.w = fmaf(x.w, wv.w, a.w);
        }
        sF[tid] = a.x + a.y + a.z + a.w;
    }
    __syncthreads();

    // ---- phase 3: scores (32-dim), j-outer, exp w/o normalize ----
    float inv0;
    {
        const float4* q4a = (const float4*)(sQt + w * 32);
        const float4* X4 = (const float4*)sX;
        float acc0[5];
#pragma unroll
        for (int i = 0; i < 5; i++) acc0[i] = 0.f;
#pragma unroll
        for (int j = 0; j < 8; j++) {
            float4 qa = q4a[j];
#pragma unroll
            for (int i = 0; i < 4; i++) {
                float4 kv = X4[(lane + 32 * i) * 9 + j];
                acc0[i] = fmaf(qa.x, kv.x, acc0[i]);
                acc0[i] = fmaf(qa.y, kv.y, acc0[i]);
                acc0[i] = fmaf(qa.z, kv.z, acc0[i]);
                acc0[i] = fmaf(qa.w, kv.w, acc0[i]);
            }
            if (lane == 0) {
                float4 kv = X4[128 * 9 + j];
                acc0[4] = fmaf(qa.x, kv.x, acc0[4]);
                acc0[4] = fmaf(qa.y, kv.y, acc0[4]);
                acc0[4] = fmaf(qa.z, kv.z, acc0[4]);
                acc0[4] = fmaf(qa.w, kv.w, acc0[4]);
            }
        }
        float s0[5];
        float lmax0 = -CUDART_INF_F;
#pragma unroll
        for (int i = 0; i < 4; i++) {
            float f = sF[lane + 32 * i];
            s0[i] = (acc0[i] + f) * 0.125f;
            lmax0 = fmaxf(lmax0, s0[i]);
        }
        if (lane == 0) {
            float f = sF[128];
            s0[4] = (acc0[4] + f) * 0.125f;
            lmax0 = fmaxf(lmax0, s0[4]);
        }
        float mx0 = warp_max(lmax0);
        float* S0 = sS + w * 132;
        float ss0 = 0.f;
#pragma unroll
        for (int i = 0; i < 4; i++) {
            float e0 = __expf(s0[i] - mx0);
            S0[lane + 32 * i] = e0;
            ss0 += e0;
        }
        if (lane == 0) {
            float e0 = __expf(s0[4] - mx0);
            S0[128] = e0;
            ss0 += e0;
        }
        ss0 = warp_sum(ss0);
        inv0 = 1.f / ss0;
    }
    __syncwarp();

    // ---- phase 4: Y32, 4-k blocked, float4 prob loads ----
    {
        const float4* S04 = (const float4*)(sS + w * 132);
        float y0a = 0.f, y0b = 0.f, y0c = 0.f, y0d = 0.f;
#pragma unroll 8
        for (int kk = 0; kk < 32; kk++) {
            float4 e0 = S04[kk];
            float x0 = sX[(4 * kk + 0) * XS + lane];
            float x1 = sX[(4 * kk + 1) * XS + lane];
            float x2 = sX[(4 * kk + 2) * XS + lane];
            float x3 = sX[(4 * kk + 3) * XS + lane];
            y0a = fmaf(e0.x, x0, y0a); y0b = fmaf(e0.y, x1, y0b);
            y0c = fmaf(e0.z, x2, y0c); y0d = fmaf(e0.w, x3, y0d);
        }
        {
            float e0 = (sS + w * 132)[128];
            float x = sX[128 * XS + lane];
            y0a = fmaf(e0, x, y0a);
        }
        sY[w * 34 + lane] = (y0a + y0b + y0c + y0d) * inv0;
    }
    __syncwarp();

    // ---- phase 5: out = Y32 @ M0f + c0 + x_q ----
    {
        const float* Y0 = sY + w * 34;
        const float2* M2 = (const float2*)g_M0f;
        float2 c0v = ((const float2*)sc0)[lane];
        float2 p0 = c0v, p1 = make_float2(0.f, 0.f);
#pragma unroll 8
        for (int j = 0; j < 32; j += 2) {
            float2 m0 = __ldg(&M2[j * 32 + lane]);
            float2 m1 = __ldg(&M2[(j + 1) * 32 + lane]);
            float y00 = Y0[j], y01 = Y0[j + 1];
            p0.x = fmaf(y00, m0.x, p0.x); p0.y = fmaf(y00, m0.y, p0.y);
            p1.x = fmaf(y01, m1.x, p1.x); p1.y = fmaf(y01, m1.y, p1.y);
        }
        const float2* xr0 = (const float2*)(sX + (1 + q) * XS);
        float2 res0 = xr0[lane & 15];   // duplicated halves
        ((float2*)(out + ((size_t)b * 129 + 1 + q) * 64))[lane] =
            make_float2(res0.x + p0.x + p1.x, res0.y + p0.y + p1.y);
    }

    // ---- phase 6 (block x==0 only): target precompute (folded reads) ----
    if (blockIdx.x == 0) {
        __syncthreads();
        if (tid < 64) {
            float acc = bq2[tid];
#pragma unroll 8
            for (int j = 0; j < 32; j++)
                acc = fmaf(sX[j], Wq2[j * 64 + tid] + Wq2[(j + 32) * 64 + tid], acc);
            sF[tid] = acc;                       // Q2
        } else if (tid < 128) {
            int d = tid - 64;
            float acc = g_c1[d];
#pragma unroll 8
            for (int j = 0; j < 32; j++)
                acc = fmaf(sX[j], g_M1[j * 64 + d] + g_M1[(j + 32) * 64 + d], acc);
            g_ta[b * 64 + d] = acc;              // t_a
        }
        __syncthreads();
        if (w < 8) {
            for (int j = w * 8; j < w * 8 + 8; j++) {
                float a = sF[lane] * Wk2[j * 64 + lane];
                a = fmaf(sF[lane + 32], Wk2[j * 64 + lane + 32], a);
                a = warp_sum(a);
                if (lane == 0) g_u[b * 64 + j] = a;
            }
        } else if (w == 8) {
            float a = 0.f;
            for (int d = lane; d < 64; d += 32) a = fmaf(sF[d], bk2[d], a);
            a = warp_sum(a);
            if (lane == 0) g_csc[b] = a;
        }
    }

    // ---- phase 7: last block per batch computes target row ----
    __threadfence();
    __syncthreads();
    if (tid == 0) sflag = (atomicAdd(&g_cnt[b], 1) == 7) ? 1 : 0;
    __syncthreads();
    if (!sflag) return;
    __threadfence();

    // tail layout (overwrites main): me 128*68, probs, u, wbuf
    float* sme   = smem;
    float* sprob = smem + 8704;
    float* su    = smem + 8832;
    float* swb   = smem + 8896;

    const float4* out4 = (const float4*)out;
    for (int t = tid; t < 128 * 16; t += 512) {
        int r = t >> 4, dd4 = t & 15;
        ((float4*)sme)[r * 17 + dd4] = out4[((size_t)b * 129 + 1 + r) * 16 + dd4];
    }
    if (tid < 64) su[tid] = g_u[b * 64 + tid];
    __syncthreads();

    float c = g_csc[b];
    float sk = 0.f;
    if (tid < 128) {
        const float4* m4 = (const float4*)(sme + tid * MEP);
        const float4* u4 = (const float4*)su;
        float4 a = make_float4(0.f, 0.f, 0.f, 0.f);
#pragma unroll
        for (int j = 0; j < 16; j++) {
            float4 m = m4[j], u = u4[j];
            a.x = fmaf(m.x, u.x, a.x);
            a.y = fmaf(m.y, u.y, a.y);
            a.z = fmaf(m.z, u.z, a.z);
            a.w = fmaf(m.w, u.w, a.w);
        }
        sk = (a.x + a.y + a.z + a.w + c) * 0.125f;
    }
    float mx = warp_max(sk);
    if (tid < 128 && lane == 0) sred[w] = mx;
    __syncthreads();
    mx = fmaxf(fmaxf(sred[0], sred[1]), fmaxf(sred[2], sred[3]));
    float ex = (tid < 128) ? __expf(sk - mx) : 0.f;
    float ss = warp_sum(ex);
    if (tid < 128 && lane == 0) sred[4 + w] = ss;
    __syncthreads();
    float tot = sred[4] + sred[5] + sred[6] + sred[7];
    if (tid < 128) sprob[tid] = ex / tot;
    __syncthreads();

    if (tid < 64) {
        float acc = 0.f;
#pragma unroll 4
        for (int k = 0; k < 128; k++)
            acc = fmaf(sprob[k], sme[k * MEP + tid], acc);
        swb[tid] = acc;
    }
    __syncthreads();

    if (tid < 64) {
        float acc = g_ta[b * 64 + tid] + g_c2[tid];
#pragma unroll 8
        for (int j = 0; j < 64; j++)
            acc = fmaf(swb[j], g_M2[j * 64 + tid], acc);
        out[(size_t)b * 129 * 64 + tid] = acc;
    }
}

// ============================================================
extern "C" void kernel_launch(void* const* d_in, const int* in_sizes, int n_in,
                              void* d_out, int out_size)
{
    const float* map_states   = (const float*)d_in[0];
    const float* agent_states = (const float*)d_in[1];
    const float* m_W1 = (const float*)d_in[2];
    const float* m_b1 = (const float*)d_in[3];
    const float* m_g1 = (const float*)d_in[4];
    const float* m_be1= (const float*)d_in[5];
    const float* m_W2 = (const float*)d_in[6];
    const float* m_b2 = (const float*)d_in[7];
    const float* m_g2 = (const float*)d_in[8];
    const float* m_be2= (const float*)d_in[9];
    const float* a_W1 = (const float*)d_in[10];
    const float* a_b1 = (const float*)d_in[11];
    const float* a_g1 = (const float*)d_in[12];
    const float* a_be1= (const float*)d_in[13];
    const float* a_W2 = (const float*)d_in[14];
    const float* a_b2 = (const float*)d_in[15];
    const float* a_g2 = (const float*)d_in[16];
    const float* a_be2= (const float*)d_in[17];
    const float* att_Wq = (const float*)d_in[18];
    const float* att_bq = (const float*)d_in[19];
    const float* att_Wk = (const float*)d_in[20];
    const float* att_bk = (const float*)d_in[21];
    const float* att_Wv = (const float*)d_in[22];
    const float* att_bv = (const float*)d_in[23];
    const float* att_Wo = (const float*)d_in[24];
    const float* att_bo = (const float*)d_in[25];
    float* out = (float*)d_out;

    cudaFuncSetAttribute(k_graph, cudaFuncAttributeMaxDynamicSharedMemorySize,
                         GRAPH_SMEM_BYTES);
    cudaFuncSetAttribute(k_attn, cudaFuncAttributeMaxDynamicSharedMemorySize,
                         ATTN_SMEM_BYTES);

    k_graph<<<292, 320, GRAPH_SMEM_BYTES>>>(
        map_states, m_W1, m_b1, m_g1, m_be1, m_W2, m_b2, m_g2, m_be2,
        agent_states, a_W1, a_b1, a_g1, a_be1, a_W2, a_b2, a_g2, a_be2,
        att_Wv, att_bv, att_Wo, att_bo,
        att_Wq, att_bq, att_Wk);

    k_attn<<<dim3(8, 32), 512, ATTN_SMEM_BYTES>>>(
        att_Wq + 2 * 4096, att_bq + 2 * 64,
        att_Wk + 2 * 4096, att_bk + 2 * 64,
        out);
}

// round 16
// speedup vs baseline: 1.0616x; 1.0616x over previous
#include <cuda_runtime.h>
#include <math.h>
#include <math_constants.h>

#define FULL 0xffffffffu

__device__ __forceinline__ float warp_sum(float v) {
#pragma unroll
    for (int o = 16; o > 0; o >>= 1) v += __shfl_xor_sync(FULL, v, o);
    return v;
}
__device__ __forceinline__ float warp_max(float v) {
#pragma unroll
    for (int o = 16; o > 0; o >>= 1) v = fmaxf(v, __shfl_xor_sync(FULL, v, o));
    return v;
}

// ---- scratch (allocation-free: __device__ globals) ----
__device__ float g_kv[32 * 129 * 64];   // row 0: target, rows 1..128: map emb (first 32 floats live)
__device__ float g_Af[32 * 32];         // A folded over both dims
__device__ float g_wf2[32];             // folded score-bias vector
__device__ float g_M0f[32 * 64];        // M0 rows folded
__device__ float g_c0[64];
__device__ float g_M1[64 * 64], g_c1[64];
__device__ float g_M2[64 * 64], g_c2[64];
__device__ float g_ta[32 * 64];
__device__ float g_u[32 * 64];
__device__ float g_csc[32];
__device__ int   g_cnt[32];

// in-thread LayerNorm + affine + relu over 32 register channels (ILP'd sums)
__device__ __forceinline__ void ln_relu32(float* h, const float* g, const float* be) {
    float p0 = 0.f, p1 = 0.f, p2 = 0.f, p3 = 0.f;
#pragma unroll
    for (int c = 0; c < 32; c += 4) { p0 += h[c]; p1 += h[c+1]; p2 += h[c+2]; p3 += h[c+3]; }
    float mu = (p0 + p1 + p2 + p3) * 0.03125f;
    float v0 = 0.f, v1 = 0.f, v2 = 0.f, v3 = 0.f;
#pragma unroll
    for (int c = 0; c < 32; c += 4) {
        float d0 = h[c] - mu, d1 = h[c+1] - mu, d2 = h[c+2] - mu, d3 = h[c+3] - mu;
        v0 = fmaf(d0, d0, v0); v1 = fmaf(d1, d1, v1);
        v2 = fmaf(d2, d2, v2); v3 = fmaf(d3, d3, v3);
    }
    float rs = rsqrtf((v0 + v1 + v2 + v3) * 0.03125f + 1e-5f);
#pragma unroll
    for (int c = 0; c < 32; c++)
        h[c] = fmaxf(fmaf((h[c] - mu) * rs, g[c], be[c]), 0.f);
}

// ============================================================
// Kernel 1: local graphs (thread-per-row) + all weight folds.
// ============================================================
constexpr int GRAPH_SMEM_FLOATS = 1792 + 320 * 36;
constexpr int GRAPH_SMEM_BYTES  = GRAPH_SMEM_FLOATS * 4;

__global__ __launch_bounds__(320) void k_graph(
    const float* __restrict__ mxs,
    const float* __restrict__ mW1, const float* __restrict__ mb1,
    const float* __restrict__ mg1, const float* __restrict__ mbe1,
    const float* __restrict__ mW2, const float* __restrict__ mb2,
    const float* __restrict__ mg2, const float* __restrict__ mbe2,
    const float* __restrict__ axs,
    const float* __restrict__ aW1, const float* __restrict__ ab1,
    const float* __restrict__ ag1, const float* __restrict__ abe1,
    const float* __restrict__ aW2, const float* __restrict__ ab2,
    const float* __restrict__ ag2, const float* __restrict__ abe2,
    const float* __restrict__ att_Wv, const float* __restrict__ att_bv,
    const float* __restrict__ att_Wo, const float* __restrict__ att_bo,
    const float* __restrict__ att_Wq, const float* __restrict__ att_bq,
    const float* __restrict__ att_Wk)
{
    extern __shared__ float sm[];
    int tid = threadIdx.x;
    int bb = blockIdx.x;

    if (bb < 256) {
        // ---------------- map path: thread = one (b,m,p) row ----------------
        float* sW1 = sm;            // 16*32
        float* sW2 = sm + 512;      // 32*32
        float* sb1 = sm + 1536; float* sg1 = sm + 1568; float* sbe1 = sm + 1600;
        float* sb2 = sm + 1632; float* sg2 = sm + 1664; float* sbe2 = sm + 1696;
        float* se  = sm + 1792;     // 320*36

        if (tid < 128) ((float4*)sW1)[tid] = ((const float4*)mW1)[tid];
        for (int t = tid; t < 256; t += 320)
            ((float4*)sW2)[t] = ((const float4*)mW2)[t];
        if (tid >= 128 && tid < 160) {
            int c = tid - 128;
            sb1[c] = mb1[c]; sg1[c] = mg1[c]; sbe1[c] = mbe1[c];
            sb2[c] = mb2[c]; sg2[c] = mg2[c]; sbe2[c] = mbe2[c];
        }
        __syncthreads();

        size_t row = (size_t)bb * 320 + tid;
        float x[16];
        {
            const float4* xg = (const float4*)(mxs + row * 16);
            float4 a = xg[0], b_ = xg[1], c = xg[2], d = xg[3];
            x[0]=a.x; x[1]=a.y; x[2]=a.z; x[3]=a.w;
            x[4]=b_.x; x[5]=b_.y; x[6]=b_.z; x[7]=b_.w;
            x[8]=c.x; x[9]=c.y; x[10]=c.z; x[11]=c.w;
            x[12]=d.x; x[13]=d.y; x[14]=d.z; x[15]=d.w;
        }

        float h[32];
#pragma unroll
        for (int c4 = 0; c4 < 8; c4++) {
            float4 b4 = ((const float4*)sb1)[c4];
            h[c4*4+0]=b4.x; h[c4*4+1]=b4.y; h[c4*4+2]=b4.z; h[c4*4+3]=b4.w;
        }
#pragma unroll
        for (int k = 0; k < 16; k++) {
            float xv = x[k];
#pragma unroll
            for (int c4 = 0; c4 < 8; c4++) {
                float4 w = ((const float4*)sW1)[k * 8 + c4];
                h[c4*4+0] = fmaf(xv, w.x, h[c4*4+0]);
                h[c4*4+1] = fmaf(xv, w.y, h[c4*4+1]);
                h[c4*4+2] = fmaf(xv, w.z, h[c4*4+2]);
                h[c4*4+3] = fmaf(xv, w.w, h[c4*4+3]);
            }
        }
        ln_relu32(h, sg1, sbe1);

        float a2[32];
#pragma unroll
        for (int c4 = 0; c4 < 8; c4++) {
            float4 b4 = ((const float4*)sb2)[c4];
            a2[c4*4+0]=b4.x; a2[c4*4+1]=b4.y; a2[c4*4+2]=b4.z; a2[c4*4+3]=b4.w;
        }
#pragma unroll
        for (int k = 0; k < 32; k++) {
            float hv = h[k];
#pragma unroll
            for (int c4 = 0; c4 < 8; c4++) {
                float4 w = ((const float4*)sW2)[k * 8 + c4];
                a2[c4*4+0] = fmaf(hv, w.x, a2[c4*4+0]);
                a2[c4*4+1] = fmaf(hv, w.y, a2[c4*4+1]);
                a2[c4*4+2] = fmaf(hv, w.z, a2[c4*4+2]);
                a2[c4*4+3] = fmaf(hv, w.w, a2[c4*4+3]);
            }
        }
        ln_relu32(a2, sg2, sbe2);

#pragma unroll
        for (int c4 = 0; c4 < 8; c4++)
            ((float4*)(se + tid * 36))[c4] =
                make_float4(a2[c4*4+0], a2[c4*4+1], a2[c4*4+2], a2[c4*4+3]);
        __syncthreads();

        int w = tid >> 5, lane = tid & 31;
        for (int g = w; g < 16; g += 10) {
            const float* base = se + (g * 20) * 36 + lane;
            float mx = base[0];
#pragma unroll
            for (int j = 1; j < 20; j++) mx = fmaxf(mx, base[j * 36]);
            int bm = bb * 16 + g;
            int b = bm >> 7, m = bm & 127;
            g_kv[((size_t)b * 129 + 1 + m) * 64 + lane] = mx;
        }
    } else if (bb < 260) {
        // ---------------- agent path (agent 0) ----------------
        float* aW1s = sm;           // 4*32
        float* aW2s = sm + 512;     // 32*32
        float* ab1s = sm + 1536; float* ag1s = sm + 1568; float* abe1s = sm + 1600;
        float* ab2s = sm + 1632; float* ag2s = sm + 1664; float* abe2s = sm + 1696;
        float* se   = sm + 1792;    // 256*36

        if (tid < 32) ((float4*)aW1s)[tid] = ((const float4*)aW1)[tid];
        else if (tid < 288) ((float4*)aW2s)[tid - 32] = ((const float4*)aW2)[tid - 32];
        if (tid >= 288) {
            int t = tid - 288;
            ab1s[t] = ab1[t]; ag1s[t] = ag1[t]; abe1s[t] = abe1[t];
            ab2s[t] = ab2[t]; ag2s[t] = ag2[t]; abe2s[t] = abe2[t];
        }
        __syncthreads();

        if (tid < 256) {
            int b0 = (bb - 256) * 8;
            int lb = tid >> 5, row = tid & 31;
            int b = b0 + lb;
            float4 xv4 = ((const float4*)(axs + (size_t)b * 4096 + row * 4))[0];

            float h[32];
#pragma unroll
            for (int c4 = 0; c4 < 8; c4++) {
                float4 b4 = ((const float4*)ab1s)[c4];
                h[c4*4+0]=b4.x; h[c4*4+1]=b4.y; h[c4*4+2]=b4.z; h[c4*4+3]=b4.w;
            }
            float xk[4] = {xv4.x, xv4.y, xv4.z, xv4.w};
#pragma unroll
            for (int k = 0; k < 4; k++) {
                float xv = xk[k];
#pragma unroll
                for (int c4 = 0; c4 < 8; c4++) {
                    float4 w = ((const float4*)aW1s)[k * 8 + c4];
                    h[c4*4+0] = fmaf(xv, w.x, h[c4*4+0]);
                    h[c4*4+1] = fmaf(xv, w.y, h[c4*4+1]);
                    h[c4*4+2] = fmaf(xv, w.z, h[c4*4+2]);
                    h[c4*4+3] = fmaf(xv, w.w, h[c4*4+3]);
                }
            }
            ln_relu32(h, ag1s, abe1s);

            float a2[32];
#pragma unroll
            for (int c4 = 0; c4 < 8; c4++) {
                float4 b4 = ((const float4*)ab2s)[c4];
                a2[c4*4+0]=b4.x; a2[c4*4+1]=b4.y; a2[c4*4+2]=b4.z; a2[c4*4+3]=b4.w;
            }
#pragma unroll
            for (int k = 0; k < 32; k++) {
                float hv = h[k];
#pragma unroll
                for (int c4 = 0; c4 < 8; c4++) {
                    float4 w = ((const float4*)aW2s)[k * 8 + c4];
                    a2[c4*4+0] = fmaf(hv, w.x, a2[c4*4+0]);
                    a2[c4*4+1] = fmaf(hv, w.y, a2[c4*4+1]);
                    a2[c4*4+2] = fmaf(hv, w.z, a2[c4*4+2]);
                    a2[c4*4+3] = fmaf(hv, w.w, a2[c4*4+3]);
                }
            }
            ln_relu32(a2, ag2s, abe2s);

#pragma unroll
            for (int c4 = 0; c4 < 8; c4++)
                ((float4*)(se + tid * 36))[c4] =
                    make_float4(a2[c4*4+0], a2[c4*4+1], a2[c4*4+2], a2[c4*4+3]);
        }
        __syncthreads();

        int w = tid >> 5, lane = tid & 31;
        if (w < 8) {
            const float* base = se + (w * 32) * 36 + lane;
            float mx = base[0];
#pragma unroll
            for (int j = 1; j < 32; j++) mx = fmaxf(mx, base[j * 36]);
            int b = (bb - 256) * 8 + w;
            g_kv[(size_t)b * 129 * 64 + lane] = mx;
        }
    } else if (bb < 284) {
        // ---------------- M folds ----------------
        float* sWo = sm;            // 4096
        float* sWv = sm + 4096;     // up to 512

        int which = bb - 260;
        int head  = which >> 3, sub = which & 7;
        const float* Wv = att_Wv + head * 4096;
        const float* Wo = att_Wo + head * 4096;
        const float* bv = att_bv + head * 64;
        const float* bo = att_bo + head * 64;

        for (int t = tid; t < 1024; t += 320)
            ((float4*)sWo)[t] = ((const float4*)Wo)[t];

        if (head == 0) {
            int r0 = sub * 4;
            for (int t = tid; t < 256; t += 320) {
                int r = t >> 6, d = t & 63;
                sWv[t] = Wv[(r0 + r) * 64 + d] + Wv[(r0 + r + 32) * 64 + d];
            }
            __syncthreads();
            for (int t = tid; t < 256; t += 320) {
                int r = t >> 6, d = t & 63;
                float acc = 0.f;
#pragma unroll 8
                for (int k = 0; k < 64; k++)
                    acc = fmaf(sWv[r * 64 + k], sWo[k * 64 + d], acc);
                g_M0f[(r0 + r) * 64 + d] = acc;
            }
            if (sub == 0 && tid >= 256) {
                int d = tid - 256;
                if (d < 64) {
                    float acc = bo[d];
#pragma unroll 8
                    for (int k = 0; k < 64; k++)
                        acc = fmaf(bv[k], sWo[k * 64 + d], acc);
                    g_c0[d] = acc;
                }
            }
        } else {
            int r0 = sub * 8;
            float* M    = (head == 1) ? g_M1 : g_M2;
            float* cvec = (head == 1) ? g_c1 : g_c2;
            if (tid < 128)
                ((float4*)sWv)[tid] = ((const float4*)(Wv + r0 * 64))[tid];
            __syncthreads();
            for (int t = tid; t < 512; t += 320) {
                int r = t >> 6, d = t & 63;
                float acc = 0.f;
#pragma unroll 8
                for (int k = 0; k < 64; k++)
                    acc = fmaf(sWv[r * 64 + k], sWo[k * 64 + d], acc);
                M[(r0 + r) * 64 + d] = acc;
            }
            if (sub == 0 && tid < 64) {
                int d = tid;
                float acc = bo[d];
#pragma unroll 8
                for (int k = 0; k < 64; k++)
                    acc = fmaf(bv[k], sWo[k * 64 + d], acc);
                cvec[d] = acc;
            }
        }
    } else {
        // ---------------- Af fold ----------------
        float* sWkTf = sm;          // 64*36
        float* sWqf  = sm + 2304;   // 4*64

        int sub = bb - 284;
        int r0 = sub * 4;
        const float* Wq0 = att_Wq;
        const float* Wk0 = att_Wk;
        const float* bq0 = att_bq;

        for (int t = tid; t < 2048; t += 320) {
            int c = t >> 6, d = t & 63;
            sWkTf[d * 36 + c] = Wk0[c * 64 + d] + Wk0[(c + 32) * 64 + d];
        }
        for (int t = tid; t < 256; t += 320) {
            int r = t >> 6, d = t & 63;
            sWqf[t] = Wq0[(r0 + r) * 64 + d] + Wq0[(r0 + r + 32) * 64 + d];
        }
        __syncthreads();

        if (tid < 128) {
            int r = tid >> 5, c = tid & 31;
            float acc = 0.f;
#pragma unroll 8
            for (int d = 0; d < 64; d++)
                acc = fmaf(sWqf[r * 64 + d], sWkTf[d * 36 + c], acc);
            g_Af[(r0 + r) * 32 + c] = acc;
        }
        if (sub == 0) {
            if (tid >= 128 && tid < 160) {
                int c = tid - 128;
                float acc = 0.f;
#pragma unroll 8
                for (int d = 0; d < 64; d++)
                    acc = fmaf(sWkTf[d * 36 + c], bq0[d], acc);
                g_wf2[c] = acc;
            } else if (tid >= 160 && tid < 192) {
                g_cnt[tid - 160] = 0;
            }
        }
    }
}

// ============================================================
// Kernel 2: attention (32-dim folded), SINGLE WAVE:
// grid (4,32) = 128 blocks <= 148 SMs.  512 threads, 16 warps,
// 2 queries per warp (32 q/block).
// ============================================================
#define XS 36      // main X row stride
#define MEP 68     // tail me row stride
constexpr int ATTN_SMEM_FLOATS = 11208;   // main layout (tail needs 8960, fits)
constexpr int ATTN_SMEM_BYTES = ATTN_SMEM_FLOATS * 4;

__global__ __launch_bounds__(512, 2)
void k_attn(
    const float* __restrict__ Wq2, const float* __restrict__ bq2,
    const float* __restrict__ Wk2, const float* __restrict__ bk2,
    float* __restrict__ out)
{
    extern __shared__ float smem[];
    // main-phase layout
    float* sX   = smem;             // 129*36 = 4644
    float* sS   = smem + 4644;      // 32*132 = 4224
    float* sY   = smem + 8868;      // 32*34  = 1088
    float* sQt  = smem + 9956;      // 32*32  = 1024
    float* sF   = smem + 10980;     // 132
    float* sWf2 = smem + 11112;     // 32
    float* sc0  = smem + 11144;     // 64
    __shared__ int sflag;
    __shared__ float sred[8];

    int b  = blockIdx.y;
    int q0 = blockIdx.x * 32;
    int tid = threadIdx.x;
    int w = tid >> 5, lane = tid & 31;

    // ---- phase 1: stage 32-dim kv tile + wf2/c0 ----
    const float4* kv4 = (const float4*)(g_kv + (size_t)b * 129 * 64);
    for (int t = tid; t < 129 * 8; t += 512) {
        int r = t >> 3, d4 = t & 7;
        ((float4*)sX)[r * 9 + d4] = kv4[r * 16 + d4];
    }
    if (tid < 32) sWf2[tid] = g_wf2[tid];
    else if (tid < 96) sc0[tid - 32] = g_c0[tid - 32];
    __syncthreads();

    // ---- phase 2: Qt' = x32 @ Af for queries 2w, 2w+1; f per key ----
    {
        const float* xq0 = sX + (1 + q0 + 2 * w) * XS;
        const float* xq1 = xq0 + XS;
        float p0 = 0.f, p1 = 0.f, r0 = 0.f, r1 = 0.f;
#pragma unroll 8
        for (int j = 0; j < 32; j += 2) {
            float a0 = __ldg(&g_Af[j * 32 + lane]);
            float a1 = __ldg(&g_Af[(j + 1) * 32 + lane]);
            p0 = fmaf(xq0[j], a0, p0); p1 = fmaf(xq0[j + 1], a1, p1);
            r0 = fmaf(xq1[j], a0, r0); r1 = fmaf(xq1[j + 1], a1, r1);
        }
        sQt[(2 * w) * 32 + lane] = p0 + p1;
        sQt[(2 * w + 1) * 32 + lane] = r0 + r1;
    }
    if (tid < 129) {
        const float4* xk4 = (const float4*)(sX + tid * XS);
        const float4* wf4 = (const float4*)sWf2;
        float4 a = make_float4(0.f, 0.f, 0.f, 0.f);
#pragma unroll
        for (int j = 0; j < 8; j++) {
            float4 x = xk4[j], wv = wf4[j];
            a.x = fmaf(x.x, wv.x, a.x);
            a.y = fmaf(x.y, wv.y, a.y);
            a.z = fmaf(x.z, wv.z, a.z);
            a.w = fmaf(x.w, wv.w, a.w);
        }
        sF[tid] = a.x + a.y + a.z + a.w;
    }
    __syncthreads();

    // ---- phase 3: scores (32-dim), 2 q/warp, j-outer, exp w/o normalize ----
    float inv0, inv1;
    {
        const float4* q4a = (const float4*)(sQt + (2 * w) * 32);
        const float4* q4b = q4a + 8;
        const float4* X4 = (const float4*)sX;
        float acc0[5], acc1[5];
#pragma unroll
        for (int i = 0; i < 5; i++) { acc0[i] = 0.f; acc1[i] = 0.f; }
#pragma unroll
        for (int j = 0; j < 8; j++) {
            float4 qa = q4a[j], qb = q4b[j];
#pragma unroll
            for (int i = 0; i < 4; i++) {
                float4 kv = X4[(lane + 32 * i) * 9 + j];
                acc0[i] = fmaf(qa.x, kv.x, acc0[i]);
                acc0[i] = fmaf(qa.y, kv.y, acc0[i]);
                acc0[i] = fmaf(qa.z, kv.z, acc0[i]);
                acc0[i] = fmaf(qa.w, kv.w, acc0[i]);
                acc1[i] = fmaf(qb.x, kv.x, acc1[i]);
                acc1[i] = fmaf(qb.y, kv.y, acc1[i]);
                acc1[i] = fmaf(qb.z, kv.z, acc1[i]);
                acc1[i] = fmaf(qb.w, kv.w, acc1[i]);
            }
            if (lane == 0) {
                float4 kv = X4[128 * 9 + j];
                acc0[4] = fmaf(qa.x, kv.x, acc0[4]);
                acc0[4] = fmaf(qa.y, kv.y, acc0[4]);
                acc0[4] = fmaf(qa.z, kv.z, acc0[4]);
                acc0[4] = fmaf(qa.w, kv.w, acc0[4]);
                acc1[4] = fmaf(qb.x, kv.x, acc1[4]);
                acc1[4] = fmaf(qb.y, kv.y, acc1[4]);
                acc1[4] = fmaf(qb.z, kv.z, acc1[4]);
                acc1[4] = fmaf(qb.w, kv.w, acc1[4]);
            }
        }
        float s0[5], s1[5];
        float lmax0 = -CUDART_INF_F, lmax1 = -CUDART_INF_F;
#pragma unroll
        for (int i = 0; i < 4; i++) {
            float f = sF[lane + 32 * i];
            s0[i] = (acc0[i] + f) * 0.125f;
            s1[i] = (acc1[i] + f) * 0.125f;
            lmax0 = fmaxf(lmax0, s0[i]);
            lmax1 = fmaxf(lmax1, s1[i]);
        }
        if (lane == 0) {
            float f = sF[128];
            s0[4] = (acc0[4] + f) * 0.125f;
            s1[4] = (acc1[4] + f) * 0.125f;
            lmax0 = fmaxf(lmax0, s0[4]);
            lmax1 = fmaxf(lmax1, s1[4]);
        }
        float mx0 = warp_max(lmax0), mx1 = warp_max(lmax1);
        float* S0 = sS + (2 * w) * 132;
        float* S1 = S0 + 132;
        float ss0 = 0.f, ss1 = 0.f;
#pragma unroll
        for (int i = 0; i < 4; i++) {
            float e0 = __expf(s0[i] - mx0);
            float e1 = __expf(s1[i] - mx1);
            S0[lane + 32 * i] = e0;
            S1[lane + 32 * i] = e1;
            ss0 += e0; ss1 += e1;
        }
        if (lane == 0) {
            float e0 = __expf(s0[4] - mx0);
            float e1 = __expf(s1[4] - mx1);
            S0[128] = e0; S1[128] = e1;
            ss0 += e0; ss1 += e1;
        }
        ss0 = warp_sum(ss0); ss1 = warp_sum(ss1);
        inv0 = 1.f / ss0; inv1 = 1.f / ss1;
    }
    __syncwarp();

    // ---- phase 4: Y32 for both queries, 4-k blocked (shared X loads) ----
    {
        const float4* S04 = (const float4*)(sS + (2 * w) * 132);
        const float4* S14 = (const float4*)(sS + (2 * w + 1) * 132);
        float y0a = 0.f, y0b = 0.f, y0c = 0.f, y0d = 0.f;
        float y1a = 0.f, y1b = 0.f, y1c = 0.f, y1d = 0.f;
#pragma unroll 8
        for (int kk = 0; kk < 32; kk++) {
            float4 e0 = S04[kk], e1 = S14[kk];
            float x0 = sX[(4 * kk + 0) * XS + lane];
            float x1 = sX[(4 * kk + 1) * XS + lane];
            float x2 = sX[(4 * kk + 2) * XS + lane];
            float x3 = sX[(4 * kk + 3) * XS + lane];
            y0a = fmaf(e0.x, x0, y0a); y0b = fmaf(e0.y, x1, y0b);
            y0c = fmaf(e0.z, x2, y0c); y0d = fmaf(e0.w, x3, y0d);
            y1a = fmaf(e1.x, x0, y1a); y1b = fmaf(e1.y, x1, y1b);
            y1c = fmaf(e1.z, x2, y1c); y1d = fmaf(e1.w, x3, y1d);
        }
        {
            float e0 = (sS + (2 * w) * 132)[128];
            float e1 = (sS + (2 * w + 1) * 132)[128];
            float x = sX[128 * XS + lane];
            y0a = fmaf(e0, x, y0a);
            y1a = fmaf(e1, x, y1a);
        }
        sY[(2 * w) * 34 + lane] = (y0a + y0b + y0c + y0d) * inv0;
        sY[(2 * w + 1) * 34 + lane] = (y1a + y1b + y1c + y1d) * inv1;
    }
    __syncwarp();

    // ---- phase 5: out = Y32 @ M0f + c0 + x_q for both queries ----
    {
        const float* Y0 = sY + (2 * w) * 34;
        const float* Y1 = sY + (2 * w + 1) * 34;
        const float2* M2 = (const float2*)g_M0f;
        float2 c0v = ((const float2*)sc0)[lane];
        float2 p0 = c0v, p1 = make_float2(0.f, 0.f);
        float2 r0 = c0v, r1 = make_float2(0.f, 0.f);
#pragma unroll 8
        for (int j = 0; j < 32; j += 2) {
            float2 m0 = __ldg(&M2[j * 32 + lane]);
            float2 m1 = __ldg(&M2[(j + 1) * 32 + lane]);
            float y00 = Y0[j], y01 = Y0[j + 1];
            float y10 = Y1[j], y11 = Y1[j + 1];
            p0.x = fmaf(y00, m0.x, p0.x); p0.y = fmaf(y00, m0.y, p0.y);
            p1.x = fmaf(y01, m1.x, p1.x); p1.y = fmaf(y01, m1.y, p1.y);
            r0.x = fmaf(y10, m0.x, r0.x); r0.y = fmaf(y10, m0.y, r0.y);
            r1.x = fmaf(y11, m1.x, r1.x); r1.y = fmaf(y11, m1.y, r1.y);
        }
        const float2* xr0 = (const float2*)(sX + (1 + q0 + 2 * w) * XS);
        const float2* xr1 = (const float2*)(sX + (1 + q0 + 2 * w + 1) * XS);
        float2 res0 = xr0[lane & 15];   // duplicated halves
        float2 res1 = xr1[lane & 15];
        ((float2*)(out + ((size_t)b * 129 + 1 + q0 + 2 * w) * 64))[lane] =
            make_float2(res0.x + p0.x + p1.x, res0.y + p0.y + p1.y);
        ((float2*)(out + ((size_t)b * 129 + 1 + q0 + 2 * w + 1) * 64))[lane] =
            make_float2(res1.x + r0.x + r1.x, res1.y + r0.y + r1.y);
    }

    // ---- phase 6 (block x==0 only): target precompute (folded reads) ----
    if (blockIdx.x == 0) {
        __syncthreads();
        if (tid < 64) {
            float acc = bq2[tid];
#pragma unroll 8
            for (int j = 0; j < 32; j++)
                acc = fmaf(sX[j], Wq2[j * 64 + tid] + Wq2[(j + 32) * 64 + tid], acc);
            sF[tid] = acc;                       // Q2
        } else if (tid < 128) {
            int d = tid - 64;
            float acc = g_c1[d];
#pragma unroll 8
            for (int j = 0; j < 32; j++)
                acc = fmaf(sX[j], g_M1[j * 64 + d] + g_M1[(j + 32) * 64 + d], acc);
            g_ta[b * 64 + d] = acc;              // t_a
        }
        __syncthreads();
        if (w < 8) {
            for (int j = w * 8; j < w * 8 + 8; j++) {
                float a = sF[lane] * Wk2[j * 64 + lane];
                a = fmaf(sF[lane + 32], Wk2[j * 64 + lane + 32], a);
                a = warp_sum(a);
                if (lane == 0) g_u[b * 64 + j] = a;
            }
        } else if (w == 8) {
            float a = 0.f;
            for (int d = lane; d < 64; d += 32) a = fmaf(sF[d], bk2[d], a);
            a = warp_sum(a);
            if (lane == 0) g_csc[b] = a;
        }
    }

    // ---- phase 7: last block per batch computes target row ----
    __threadfence();
    __syncthreads();
    if (tid == 0) sflag = (atomicAdd(&g_cnt[b], 1) == 3) ? 1 : 0;
    __syncthreads();
    if (!sflag) return;
    __threadfence();

    // tail layout (overwrites main): me 128*68, probs, u, wbuf
    float* sme   = smem;
    float* sprob = smem + 8704;
    float* su    = smem + 8832;
    float* swb   = smem + 8896;

    const float4* out4 = (const float4*)out;
    for (int t = tid; t < 128 * 16; t += 512) {
        int r = t >> 4, dd4 = t & 15;
        ((float4*)sme)[r * 17 + dd4] = out4[((size_t)b * 129 + 1 + r) * 16 + dd4];
    }
    if (tid < 64) su[tid] = g_u[b * 64 + tid];
    __syncthreads();

    float c = g_csc[b];
    float sk = 0.f;
    if (tid < 128) {
        const float4* m4 = (const float4*)(sme + tid * MEP);
        const float4* u4 = (const float4*)su;
        float4 a = make_float4(0.f, 0.f, 0.f, 0.f);
#pragma unroll
        for (int j = 0; j < 16; j++) {
            float4 m = m4[j], u = u4[j];
            a.x = fmaf(m.x, u.x, a.x);
            a.y = fmaf(m.y, u.y, a.y);
            a.z = fmaf(m.z, u.z, a.z);
            a.w = fmaf(m.w, u.w, a.w);
        }
        sk = (a.x + a.y + a.z + a.w + c) * 0.125f;
    }
    float mx = warp_max(sk);
    if (tid < 128 && lane == 0) sred[w] = mx;
    __syncthreads();
    mx = fmaxf(fmaxf(sred[0], sred[1]), fmaxf(sred[2], sred[3]));
    float ex = (tid < 128) ? __expf(sk - mx) : 0.f;
    float ss = warp_sum(ex);
    if (tid < 128 && lane == 0) sred[4 + w] = ss;
    __syncthreads();
    float tot = sred[4] + sred[5] + sred[6] + sred[7];
    if (tid < 128) sprob[tid] = ex / tot;
    __syncthreads();

    if (tid < 64) {
        float acc = 0.f;
#pragma unroll 4
        for (int k = 0; k < 128; k++)
            acc = fmaf(sprob[k], sme[k * MEP + tid], acc);
        swb[tid] = acc;
    }
    __syncthreads();

    if (tid < 64) {
        float acc = g_ta[b * 64 + tid] + g_c2[tid];
#pragma unroll 8
        for (int j = 0; j < 64; j++)
            acc = fmaf(swb[j], g_M2[j * 64 + tid], acc);
        out[(size_t)b * 129 * 64 + tid] = acc;
    }
}

// ============================================================
extern "C" void kernel_launch(void* const* d_in, const int* in_sizes, int n_in,
                              void* d_out, int out_size)
{
    const float* map_states   = (const float*)d_in[0];
    const float* agent_states = (const float*)d_in[1];
    const float* m_W1 = (const float*)d_in[2];
    const float* m_b1 = (const float*)d_in[3];
    const float* m_g1 = (const float*)d_in[4];
    const float* m_be1= (const float*)d_in[5];
    const float* m_W2 = (const float*)d_in[6];
    const float* m_b2 = (const float*)d_in[7];
    const float* m_g2 = (const float*)d_in[8];
    const float* m_be2= (const float*)d_in[9];
    const float* a_W1 = (const float*)d_in[10];
    const float* a_b1 = (const float*)d_in[11];
    const float* a_g1 = (const float*)d_in[12];
    const float* a_be1= (const float*)d_in[13];
    const float* a_W2 = (const float*)d_in[14];
    const float* a_b2 = (const float*)d_in[15];
    const float* a_g2 = (const float*)d_in[16];
    const float* a_be2= (const float*)d_in[17];
    const float* att_Wq = (const float*)d_in[18];
    const float* att_bq = (const float*)d_in[19];
    const float* att_Wk = (const float*)d_in[20];
    const float* att_bk = (const float*)d_in[21];
    const float* att_Wv = (const float*)d_in[22];
    const float* att_bv = (const float*)d_in[23];
    const float* att_Wo = (const float*)d_in[24];
    const float* att_bo = (const float*)d_in[25];
    float* out = (float*)d_out;

    cudaFuncSetAttribute(k_graph, cudaFuncAttributeMaxDynamicSharedMemorySize,
                         GRAPH_SMEM_BYTES);
    cudaFuncSetAttribute(k_attn, cudaFuncAttributeMaxDynamicSharedMemorySize,
                         ATTN_SMEM_BYTES);

    k_graph<<<292, 320, GRAPH_SMEM_BYTES>>>(
        map_states, m_W1, m_b1, m_g1, m_be1, m_W2, m_b2, m_g2, m_be2,
        agent_states, a_W1, a_b1, a_g1, a_be1, a_W2, a_b2, a_g2, a_be2,
        att_Wv, att_bv, att_Wo, att_bo,
        att_Wq, att_bq, att_Wk);

    k_attn<<<dim3(4, 32), 512, ATTN_SMEM_BYTES>>>(
        att_Wq + 2 * 4096, att_bq + 2 * 64,
        att_Wk + 2 * 4096, att_bk + 2 * 64,
        out);
}